// round 2
// baseline (speedup 1.0000x reference)
#include <cuda_runtime.h>
#include <math.h>

#define NB 2
#define NS 2048
#define ND 1024
#define NH 16
#define NDK 64
#define NM (NB*NS)   // 4096

// Scratch (allocation-free): Q, K, V, attention output, each 16 MB fp32.
__device__ float g_q[(size_t)NM * ND];
__device__ float g_k[(size_t)NM * ND];
__device__ float g_v[(size_t)NM * ND];
__device__ float g_attn[(size_t)NM * ND];

// ---------------------------------------------------------------------------
// SGEMM: C[M,N] = A[M,K] @ W[K,N], fp32, 128x128x8 tile, 256 threads, 8x8 micro
// ---------------------------------------------------------------------------
__global__ __launch_bounds__(256, 2)
void sgemm_kernel(const float* __restrict__ A, const float* __restrict__ W,
                  float* __restrict__ C, int M, int N, int K)
{
    __shared__ float As[8][128];
    __shared__ float Ws[8][128];

    const int tid = threadIdx.x;
    const int tr  = tid >> 4;   // 0..15 -> 8 output rows each
    const int tc  = tid & 15;   // 0..15 -> 8 output cols each

    const float* Ab = A + (size_t)blockIdx.y * 128 * K;
    const float* Wb = W + (size_t)blockIdx.x * 128;

    float acc[8][8];
    #pragma unroll
    for (int i = 0; i < 8; i++)
        #pragma unroll
        for (int j = 0; j < 8; j++) acc[i][j] = 0.0f;

    const int aRow = tid >> 1;          // 0..127
    const int aCol = (tid & 1) << 2;    // 0 or 4
    const int wRow = tid >> 5;          // 0..7
    const int wCol = (tid & 31) << 2;   // 0..124

    for (int k0 = 0; k0 < K; k0 += 8) {
        float4 a = *(const float4*)(Ab + (size_t)aRow * K + k0 + aCol);
        As[aCol + 0][aRow] = a.x;
        As[aCol + 1][aRow] = a.y;
        As[aCol + 2][aRow] = a.z;
        As[aCol + 3][aRow] = a.w;
        *(float4*)(&Ws[wRow][wCol]) =
            *(const float4*)(Wb + (size_t)(k0 + wRow) * N + wCol);
        __syncthreads();

        #pragma unroll
        for (int kk = 0; kk < 8; kk++) {
            float ra[8], rw[8];
            *(float4*)(ra)     = *(const float4*)(&As[kk][tr * 8]);
            *(float4*)(ra + 4) = *(const float4*)(&As[kk][tr * 8 + 4]);
            *(float4*)(rw)     = *(const float4*)(&Ws[kk][tc * 8]);
            *(float4*)(rw + 4) = *(const float4*)(&Ws[kk][tc * 8 + 4]);
            #pragma unroll
            for (int i = 0; i < 8; i++)
                #pragma unroll
                for (int j = 0; j < 8; j++)
                    acc[i][j] = fmaf(ra[i], rw[j], acc[i][j]);
        }
        __syncthreads();
    }

    float* Cb = C + (size_t)(blockIdx.y * 128 + tr * 8) * N
                  + blockIdx.x * 128 + tc * 8;
    #pragma unroll
    for (int i = 0; i < 8; i++) {
        *(float4*)(Cb + (size_t)i * N) =
            make_float4(acc[i][0], acc[i][1], acc[i][2], acc[i][3]);
        *(float4*)(Cb + (size_t)i * N + 4) =
            make_float4(acc[i][4], acc[i][5], acc[i][6], acc[i][7]);
    }
}

// ---------------------------------------------------------------------------
// RoPE over full D=1024 dim (as the reference does, BEFORE head split).
// Double-precision trig: immune to fast-math, matches fp32-angle reference.
// ---------------------------------------------------------------------------
__global__ void rope_kernel()
{
    const int NPAIR = ND / 2;
    int p = blockIdx.x * blockDim.x + threadIdx.x;
    if (p >= NM * NPAIR) return;
    int row  = p / NPAIR;
    int pr   = p - row * NPAIR;     // pair index 0..511
    int spos = row & (NS - 1);      // sequence position

    // inv_freq = 10000^(-(2*pr)/D), computed in double, rounded to fp32
    double fd = exp(((double)(-2 * pr) / (double)ND) * 9.210340371976184);
    float freq = (float)fd;
    float ang = (float)spos * freq;   // fp32 product, same rounding as reference
    double sd, cd;
    sincos((double)ang, &sd, &cd);    // accurate trig of the fp32 angle
    float sn = (float)sd, cs = (float)cd;

    size_t idx = (size_t)row * ND + 2 * pr;
    float2 q = *(float2*)(&g_q[idx]);
    float2 k = *(float2*)(&g_k[idx]);
    *(float2*)(&g_q[idx]) = make_float2(q.x * cs - q.y * sn, q.x * sn + q.y * cs);
    *(float2*)(&g_k[idx]) = make_float2(k.x * cs - k.y * sn, k.x * sn + k.y * cs);
}

// ---------------------------------------------------------------------------
// Flash attention, causal. 64 q-rows per block, KV tiles of 64, DK=64.
// 256 threads, thread (tr,tc) owns 4 q-rows x 4 cols.
// Q and K stored transposed [d][seq] with float4-granularity XOR swizzle:
//   phys col4 = (col>>2) ^ (dd>>2)   -> conflict-free loads AND stores.
// KPs buffer is reused for K tile then P^T (saves 16KB -> fits 48KB static).
// ---------------------------------------------------------------------------
__device__ __forceinline__ int sw_idx(int dd, int col)
{
    return dd * 64 + ((((col >> 2) ^ (dd >> 2)) & 15) << 2) + (col & 3);
}

__global__ __launch_bounds__(256)
void flash_kernel(const float* __restrict__ Q, const float* __restrict__ K,
                  const float* __restrict__ V, float* __restrict__ O)
{
    __shared__ float Qs[64 * 64];
    __shared__ float KPs[64 * 64];
    __shared__ float Vs[64 * 64];

    const int tid = threadIdx.x;
    const int tr  = tid >> 4;
    const int tc  = tid & 15;
    const int qt  = (int)gridDim.x - 1 - (int)blockIdx.x;  // big tiles first
    const int bh  = blockIdx.y;
    const int b   = bh >> 4;
    const int h   = bh & 15;
    const size_t base = (size_t)b * NS * ND + (size_t)h * NDK;
    const int q0 = qt * 64;

    // Load Q tile, transposed+swizzled, pre-scaled by 1/sqrt(DK)=0.125
    #pragma unroll
    for (int ps = 0; ps < 4; ps++) {
        int e  = ps * 256 + tid;
        int qr = e >> 4;
        int d0 = (e & 15) << 2;
        float4 qv = *(const float4*)(Q + base + (size_t)(q0 + qr) * ND + d0);
        Qs[sw_idx(d0 + 0, qr)] = qv.x * 0.125f;
        Qs[sw_idx(d0 + 1, qr)] = qv.y * 0.125f;
        Qs[sw_idx(d0 + 2, qr)] = qv.z * 0.125f;
        Qs[sw_idx(d0 + 3, qr)] = qv.w * 0.125f;
    }

    float m_i[4], l_i[4], o_acc[4][4];
    #pragma unroll
    for (int i = 0; i < 4; i++) {
        m_i[i] = -INFINITY;
        l_i[i] = 0.0f;
        #pragma unroll
        for (int j = 0; j < 4; j++) o_acc[i][j] = 0.0f;
    }
    __syncthreads();

    for (int t = 0; t <= qt; t++) {
        const int k0 = t * 64;
        // Load K (transposed+swizzled) and V (row-major) tiles
        #pragma unroll
        for (int ps = 0; ps < 4; ps++) {
            int e  = ps * 256 + tid;
            int kr = e >> 4;
            int d0 = (e & 15) << 2;
            float4 kv = *(const float4*)(K + base + (size_t)(k0 + kr) * ND + d0);
            KPs[sw_idx(d0 + 0, kr)] = kv.x;
            KPs[sw_idx(d0 + 1, kr)] = kv.y;
            KPs[sw_idx(d0 + 2, kr)] = kv.z;
            KPs[sw_idx(d0 + 3, kr)] = kv.w;
            float4 vv = *(const float4*)(V + base + (size_t)(k0 + kr) * ND + d0);
            *(float4*)(&Vs[kr * 64 + d0]) = vv;
        }
        __syncthreads();

        // S = Q K^T  (4x4 per thread)
        float s[4][4];
        #pragma unroll
        for (int i = 0; i < 4; i++)
            #pragma unroll
            for (int j = 0; j < 4; j++) s[i][j] = 0.0f;

        #pragma unroll 8
        for (int dd = 0; dd < 64; dd++) {
            float4 qv = *(const float4*)(&Qs[dd * 64 + (((tr ^ (dd >> 2)) & 15) << 2)]);
            float4 kv = *(const float4*)(&KPs[dd * 64 + (((tc ^ (dd >> 2)) & 15) << 2)]);
            float qa[4] = {qv.x, qv.y, qv.z, qv.w};
            float ka[4] = {kv.x, kv.y, kv.z, kv.w};
            #pragma unroll
            for (int i = 0; i < 4; i++)
                #pragma unroll
                for (int j = 0; j < 4; j++)
                    s[i][j] = fmaf(qa[i], ka[j], s[i][j]);
        }

        if (t == qt) {  // diagonal tile: causal mask
            #pragma unroll
            for (int i = 0; i < 4; i++)
                #pragma unroll
                for (int j = 0; j < 4; j++)
                    if (tc * 4 + j > tr * 4 + i) s[i][j] = -INFINITY;
        }

        // Online softmax update (rows shared by 16-lane groups)
        #pragma unroll
        for (int i = 0; i < 4; i++) {
            float mx = fmaxf(fmaxf(s[i][0], s[i][1]), fmaxf(s[i][2], s[i][3]));
            #pragma unroll
            for (int o = 1; o < 16; o <<= 1)
                mx = fmaxf(mx, __shfl_xor_sync(0xffffffffu, mx, o));
            float mn = fmaxf(m_i[i], mx);
            float sum = 0.0f;
            #pragma unroll
            for (int j = 0; j < 4; j++) {
                s[i][j] = __expf(s[i][j] - mn);   // p_ij (0 for masked)
                sum += s[i][j];
            }
            #pragma unroll
            for (int o = 1; o < 16; o <<= 1)
                sum += __shfl_xor_sync(0xffffffffu, sum, o);
            float scl = __expf(m_i[i] - mn);      // 0 on first tile
            l_i[i] = l_i[i] * scl + sum;
            m_i[i] = mn;
            #pragma unroll
            for (int j = 0; j < 4; j++) o_acc[i][j] *= scl;
        }

        __syncthreads();  // everyone done reading K from KPs
        // Store P^T (row = k index, col = q index), same swizzle
        #pragma unroll
        for (int j = 0; j < 4; j++) {
            int kk = tc * 4 + j;
            int ro = kk * 64 + (((tr ^ (kk >> 2)) & 15) << 2);
            #pragma unroll
            for (int i = 0; i < 4; i++) KPs[ro + i] = s[i][j];
        }
        __syncthreads();

        // O += P @ V
        #pragma unroll 8
        for (int kk = 0; kk < 64; kk++) {
            float4 pv = *(const float4*)(&KPs[kk * 64 + (((tr ^ (kk >> 2)) & 15) << 2)]);
            float4 vv = *(const float4*)(&Vs[kk * 64 + tc * 4]);
            float pa[4] = {pv.x, pv.y, pv.z, pv.w};
            float va[4] = {vv.x, vv.y, vv.z, vv.w};
            #pragma unroll
            for (int i = 0; i < 4; i++)
                #pragma unroll
                for (int j = 0; j < 4; j++)
                    o_acc[i][j] = fmaf(pa[i], va[j], o_acc[i][j]);
        }
        __syncthreads();  // before next tile overwrites Vs/KPs
    }

    // Epilogue: normalize and write to [b, s, h*DK + dk] layout
    #pragma unroll
    for (int i = 0; i < 4; i++) {
        float inv = 1.0f / l_i[i];
        float4 o = make_float4(o_acc[i][0] * inv, o_acc[i][1] * inv,
                               o_acc[i][2] * inv, o_acc[i][3] * inv);
        *(float4*)(O + base + (size_t)(q0 + tr * 4 + i) * ND + tc * 4) = o;
    }
}

// ---------------------------------------------------------------------------
extern "C" void kernel_launch(void* const* d_in, const int* in_sizes, int n_in,
                              void* d_out, int out_size)
{
    const float* x  = (const float*)d_in[0];
    const float* Wq = (const float*)d_in[1];
    const float* Wk = (const float*)d_in[2];
    const float* Wv = (const float*)d_in[3];
    const float* Wo = (const float*)d_in[4];
    float* out = (float*)d_out;

    float *pq, *pk, *pv, *pa;
    cudaGetSymbolAddress((void**)&pq, g_q);
    cudaGetSymbolAddress((void**)&pk, g_k);
    cudaGetSymbolAddress((void**)&pv, g_v);
    cudaGetSymbolAddress((void**)&pa, g_attn);

    dim3 gg(ND / 128, NM / 128);  // (8, 32)
    sgemm_kernel<<<gg, 256>>>(x, Wq, pq, NM, ND, ND);
    sgemm_kernel<<<gg, 256>>>(x, Wk, pk, NM, ND, ND);
    sgemm_kernel<<<gg, 256>>>(x, Wv, pv, NM, ND, ND);

    rope_kernel<<<(NM * (ND / 2)) / 256, 256>>>();

    flash_kernel<<<dim3(NS / 64, NB * NH), 256>>>(pq, pk, pv, pa);

    sgemm_kernel<<<gg, 256>>>(pa, Wo, out, NM, ND, ND);
}

// round 3
// speedup vs baseline: 2.8764x; 2.8764x over previous
#include <cuda_runtime.h>
#include <math.h>
#include <stdint.h>

#define NB 2
#define NS 2048
#define ND 1024
#define NH 16
#define NDK 64
#define NM (NB*NS)   // 4096

// Scratch (allocation-free)
__device__ float g_q[(size_t)NM * ND];
__device__ float g_k[(size_t)NM * ND];
__device__ float g_v[(size_t)NM * ND];
__device__ float g_attn[(size_t)NM * ND];
__device__ float g_wt[(size_t)ND * ND];     // transposed weight (reused serially)
__device__ float g_vt[(size_t)NM * ND];     // V transposed: [b][h][d][s]

__device__ __forceinline__ float to_tf32(float x)
{
    uint32_t u;
    asm("cvt.rna.tf32.f32 %0, %1;" : "=r"(u) : "f"(x));
    return __uint_as_float(u);
}

__device__ __forceinline__ void mma_tf32(float& d0, float& d1, float& d2, float& d3,
                                         uint32_t a0, uint32_t a1, uint32_t a2, uint32_t a3,
                                         uint32_t b0, uint32_t b1)
{
    asm volatile(
        "mma.sync.aligned.m16n8k8.row.col.f32.tf32.tf32.f32 "
        "{%0,%1,%2,%3}, {%4,%5,%6,%7}, {%8,%9}, {%0,%1,%2,%3};"
        : "+f"(d0), "+f"(d1), "+f"(d2), "+f"(d3)
        : "r"(a0), "r"(a1), "r"(a2), "r"(a3), "r"(b0), "r"(b1));
}

// ---------------------------------------------------------------------------
// Weight transpose: out[n*ND + k] = in[k*ND + n]   (ND x ND)
// ---------------------------------------------------------------------------
__global__ void transpose_w(const float* __restrict__ in, float* __restrict__ outp)
{
    __shared__ float t[32][33];
    int x = blockIdx.x * 32 + threadIdx.x;
    int y0 = blockIdx.y * 32;
    #pragma unroll
    for (int i = threadIdx.y; i < 32; i += 8)
        t[i][threadIdx.x] = in[(size_t)(y0 + i) * ND + x];
    __syncthreads();
    int ox = y0 + threadIdx.x;
    int oy0 = blockIdx.x * 32;
    #pragma unroll
    for (int i = threadIdx.y; i < 32; i += 8)
        outp[(size_t)(oy0 + i) * ND + ox] = t[threadIdx.x][i];
}

// ---------------------------------------------------------------------------
// V transpose: g_vt[bh][d][s] = g_v[b][s][h*64 + d]
// ---------------------------------------------------------------------------
__global__ void transpose_v()
{
    __shared__ float t[32][33];
    int bh = blockIdx.z;
    int b = bh >> 4, h = bh & 15;
    int s0 = blockIdx.x * 32, d0 = blockIdx.y * 32;
    #pragma unroll
    for (int i = threadIdx.y; i < 32; i += 8)
        t[i][threadIdx.x] = g_v[(size_t)(b * NS + s0 + i) * ND + h * NDK + d0 + threadIdx.x];
    __syncthreads();
    #pragma unroll
    for (int i = threadIdx.y; i < 32; i += 8)
        g_vt[((size_t)bh * NDK + d0 + i) * NS + s0 + threadIdx.x] = t[threadIdx.x][i];
}

// ---------------------------------------------------------------------------
// tf32 GEMM: C[M,N] = A[M,K] @ W[K,N], with Wt = W^T ([N][K] row-major).
// 128x128 CTA tile, 8 warps of 64x32, k-step 32, mma.m16n8k8.
// smem strides 36 (== 4 mod 32) -> conflict-free fragment loads.
// ---------------------------------------------------------------------------
__global__ __launch_bounds__(256)
void gemm_tf32(const float* __restrict__ A, const float* __restrict__ Wt,
               float* __restrict__ C, int M, int N, int K)
{
    __shared__ float As[128 * 36];
    __shared__ float Bs[128 * 36];

    const int tid = threadIdx.x;
    const int warp = tid >> 5, lane = tid & 31;
    const int g = lane >> 2, tg = lane & 3;
    const int wm = (warp >> 2) << 6;   // 0 or 64
    const int wn = (warp & 3) << 5;    // 0,32,64,96

    const float* Ab = A + (size_t)(blockIdx.y * 128) * K;
    const float* Bb = Wt + (size_t)(blockIdx.x * 128) * K;

    float acc[4][4][4];
    #pragma unroll
    for (int mi = 0; mi < 4; mi++)
        #pragma unroll
        for (int ni = 0; ni < 4; ni++)
            #pragma unroll
            for (int r = 0; r < 4; r++) acc[mi][ni][r] = 0.0f;

    const int lr = tid >> 3;          // 0..31
    const int lc = (tid & 7) << 2;    // 0..28

    for (int k0 = 0; k0 < K; k0 += 32) {
        #pragma unroll
        for (int p = 0; p < 4; p++) {
            int row = lr + 32 * p;
            float4 a = *(const float4*)(Ab + (size_t)row * K + k0 + lc);
            float4 bq = *(const float4*)(Bb + (size_t)row * K + k0 + lc);
            *(float4*)(&As[row * 36 + lc]) =
                make_float4(to_tf32(a.x), to_tf32(a.y), to_tf32(a.z), to_tf32(a.w));
            *(float4*)(&Bs[row * 36 + lc]) =
                make_float4(to_tf32(bq.x), to_tf32(bq.y), to_tf32(bq.z), to_tf32(bq.w));
        }
        __syncthreads();

        #pragma unroll
        for (int c = 0; c < 4; c++) {
            uint32_t af[4][4];
            #pragma unroll
            for (int mi = 0; mi < 4; mi++) {
                const float* q = &As[(wm + mi * 16 + g) * 36 + c * 8 + tg];
                af[mi][0] = __float_as_uint(q[0]);
                af[mi][1] = __float_as_uint(q[8 * 36]);
                af[mi][2] = __float_as_uint(q[4]);
                af[mi][3] = __float_as_uint(q[8 * 36 + 4]);
            }
            #pragma unroll
            for (int ni = 0; ni < 4; ni++) {
                const float* q = &Bs[(wn + ni * 8 + g) * 36 + c * 8 + tg];
                uint32_t b0 = __float_as_uint(q[0]);
                uint32_t b1 = __float_as_uint(q[4]);
                #pragma unroll
                for (int mi = 0; mi < 4; mi++)
                    mma_tf32(acc[mi][ni][0], acc[mi][ni][1], acc[mi][ni][2], acc[mi][ni][3],
                             af[mi][0], af[mi][1], af[mi][2], af[mi][3], b0, b1);
            }
        }
        __syncthreads();
    }

    #pragma unroll
    for (int mi = 0; mi < 4; mi++) {
        int row = blockIdx.y * 128 + wm + mi * 16 + g;
        #pragma unroll
        for (int ni = 0; ni < 4; ni++) {
            int col = blockIdx.x * 128 + wn + ni * 8 + tg * 2;
            *(float2*)(C + (size_t)row * N + col) =
                make_float2(acc[mi][ni][0], acc[mi][ni][1]);
            *(float2*)(C + (size_t)(row + 8) * N + col) =
                make_float2(acc[mi][ni][2], acc[mi][ni][3]);
        }
    }
}

// ---------------------------------------------------------------------------
// RoPE (unchanged, double-precision trig — proven 1e-6 accurate)
// ---------------------------------------------------------------------------
__global__ void rope_kernel()
{
    const int NPAIR = ND / 2;
    int p = blockIdx.x * blockDim.x + threadIdx.x;
    if (p >= NM * NPAIR) return;
    int row = p / NPAIR;
    int pr  = p - row * NPAIR;
    int spos = row & (NS - 1);

    double fd = exp(((double)(-2 * pr) / (double)ND) * 9.210340371976184);
    float freq = (float)fd;
    float ang = (float)spos * freq;
    double sd, cd;
    sincos((double)ang, &sd, &cd);
    float sn = (float)sd, cs = (float)cd;

    size_t idx = (size_t)row * ND + 2 * pr;
    float2 q = *(float2*)(&g_q[idx]);
    float2 k = *(float2*)(&g_k[idx]);
    *(float2*)(&g_q[idx]) = make_float2(q.x * cs - q.y * sn, q.x * sn + q.y * cs);
    *(float2*)(&g_k[idx]) = make_float2(k.x * cs - k.y * sn, k.x * sn + k.y * cs);
}

// ---------------------------------------------------------------------------
// Flash attention with tf32 mma. 128 q-rows/block, 64-kv tiles, DK=64.
// 8 warps x (16 q-rows x 64 cols). K natural layout == B col-major frag.
// V pre-transposed globally. P stays in registers (C-frag -> A-frag shuffles).
// smem stride 68 (== 4 mod 32) -> conflict-free fragment loads.
// ---------------------------------------------------------------------------
extern __shared__ float fsm[];

__global__ __launch_bounds__(256)
void flash_tf32(const float* __restrict__ Q, const float* __restrict__ K,
                float* __restrict__ O)
{
    float* Qs = fsm;               // [128][68]
    float* Ks = fsm + 128 * 68;    // [64][68]   (natural [kv][d])
    float* Vs = Ks + 64 * 68;      // [64][68]   (Vt: [d][kv])

    const int tid = threadIdx.x;
    const int warp = tid >> 5, lane = tid & 31;
    const int g = lane >> 2, tg = lane & 3;
    const int qt = (int)gridDim.x - 1 - (int)blockIdx.x;   // big tiles first
    const int bh = blockIdx.y;
    const int b = bh >> 4, h = bh & 15;
    const size_t base = (size_t)b * NS * ND + (size_t)h * NDK;
    const int q0 = qt * 128;
    const int wm = warp * 16;

    // Load Q tile (scaled by 1/8, tf32)
    {
        int r = tid >> 4, c = (tid & 15) << 2;
        #pragma unroll
        for (int p = 0; p < 8; p++) {
            int row = r + 16 * p;
            float4 qv = *(const float4*)(Q + base + (size_t)(q0 + row) * ND + c);
            *(float4*)(&Qs[row * 68 + c]) =
                make_float4(to_tf32(qv.x * 0.125f), to_tf32(qv.y * 0.125f),
                            to_tf32(qv.z * 0.125f), to_tf32(qv.w * 0.125f));
        }
    }

    float m0 = -INFINITY, m1 = -INFINITY, l0 = 0.0f, l1 = 0.0f;
    float of[8][4];
    #pragma unroll
    for (int f = 0; f < 8; f++)
        #pragma unroll
        for (int r = 0; r < 4; r++) of[f][r] = 0.0f;

    const int nt = 2 * qt + 2;
    for (int t = 0; t < nt; t++) {
        const int k0 = 64 * t;
        // Load K (natural) and Vt tiles
        {
            int r = tid >> 4, c = (tid & 15) << 2;
            #pragma unroll
            for (int p = 0; p < 4; p++) {
                int row = r + 16 * p;
                float4 kv = *(const float4*)(K + base + (size_t)(k0 + row) * ND + c);
                *(float4*)(&Ks[row * 68 + c]) =
                    make_float4(to_tf32(kv.x), to_tf32(kv.y), to_tf32(kv.z), to_tf32(kv.w));
                float4 vv = *(const float4*)(&g_vt[((size_t)bh * NDK + row) * NS + k0 + c]);
                *(float4*)(&Vs[row * 68 + c]) =
                    make_float4(to_tf32(vv.x), to_tf32(vv.y), to_tf32(vv.z), to_tf32(vv.w));
            }
        }
        __syncthreads();

        // S = Q K^T
        float sf[8][4];
        #pragma unroll
        for (int f = 0; f < 8; f++)
            #pragma unroll
            for (int r = 0; r < 4; r++) sf[f][r] = 0.0f;

        #pragma unroll
        for (int c = 0; c < 8; c++) {
            const float* qa = &Qs[(wm + g) * 68 + c * 8 + tg];
            uint32_t a0 = __float_as_uint(qa[0]);
            uint32_t a1 = __float_as_uint(qa[8 * 68]);
            uint32_t a2 = __float_as_uint(qa[4]);
            uint32_t a3 = __float_as_uint(qa[8 * 68 + 4]);
            #pragma unroll
            for (int f = 0; f < 8; f++) {
                const float* kb = &Ks[(f * 8 + g) * 68 + c * 8 + tg];
                mma_tf32(sf[f][0], sf[f][1], sf[f][2], sf[f][3],
                         a0, a1, a2, a3,
                         __float_as_uint(kb[0]), __float_as_uint(kb[4]));
            }
        }

        // Causal mask (only the last two tiles can touch the diagonal)
        if (t >= 2 * qt) {
            int rlo = q0 + wm + g, rhi = rlo + 8;
            #pragma unroll
            for (int f = 0; f < 8; f++) {
                int col = k0 + f * 8 + tg * 2;
                if (col     > rlo) sf[f][0] = -INFINITY;
                if (col + 1 > rlo) sf[f][1] = -INFINITY;
                if (col     > rhi) sf[f][2] = -INFINITY;
                if (col + 1 > rhi) sf[f][3] = -INFINITY;
            }
        }

        // Online softmax (rows split across quads: shfl_xor 1,2)
        float mx0 = -INFINITY, mx1 = -INFINITY;
        #pragma unroll
        for (int f = 0; f < 8; f++) {
            mx0 = fmaxf(mx0, fmaxf(sf[f][0], sf[f][1]));
            mx1 = fmaxf(mx1, fmaxf(sf[f][2], sf[f][3]));
        }
        mx0 = fmaxf(mx0, __shfl_xor_sync(0xffffffffu, mx0, 1));
        mx0 = fmaxf(mx0, __shfl_xor_sync(0xffffffffu, mx0, 2));
        mx1 = fmaxf(mx1, __shfl_xor_sync(0xffffffffu, mx1, 1));
        mx1 = fmaxf(mx1, __shfl_xor_sync(0xffffffffu, mx1, 2));
        float mn0 = fmaxf(m0, mx0), mn1 = fmaxf(m1, mx1);
        float s0 = 0.0f, s1 = 0.0f;
        #pragma unroll
        for (int f = 0; f < 8; f++) {
            sf[f][0] = __expf(sf[f][0] - mn0); s0 += sf[f][0];
            sf[f][1] = __expf(sf[f][1] - mn0); s0 += sf[f][1];
            sf[f][2] = __expf(sf[f][2] - mn1); s1 += sf[f][2];
            sf[f][3] = __expf(sf[f][3] - mn1); s1 += sf[f][3];
        }
        s0 += __shfl_xor_sync(0xffffffffu, s0, 1);
        s0 += __shfl_xor_sync(0xffffffffu, s0, 2);
        s1 += __shfl_xor_sync(0xffffffffu, s1, 1);
        s1 += __shfl_xor_sync(0xffffffffu, s1, 2);
        float e0 = __expf(m0 - mn0), e1 = __expf(m1 - mn1);
        l0 = l0 * e0 + s0; l1 = l1 * e1 + s1;
        m0 = mn0; m1 = mn1;
        #pragma unroll
        for (int f = 0; f < 8; f++) {
            of[f][0] *= e0; of[f][1] *= e0;
            of[f][2] *= e1; of[f][3] *= e1;
        }

        // P -> tf32
        #pragma unroll
        for (int f = 0; f < 8; f++)
            #pragma unroll
            for (int r = 0; r < 4; r++) sf[f][r] = to_tf32(sf[f][r]);

        // O += P V  (P A-frags assembled by intra-quad shuffles)
        const int m1lane = (lane & ~3) | (tg >> 1);
        const int m2lane = m1lane + 2;
        const bool odd = (tg & 1);
        #pragma unroll
        for (int c = 0; c < 8; c++) {
            float p0 = __shfl_sync(0xffffffffu, sf[c][0], m1lane);
            float p1 = __shfl_sync(0xffffffffu, sf[c][1], m1lane);
            float p2 = __shfl_sync(0xffffffffu, sf[c][2], m1lane);
            float p3 = __shfl_sync(0xffffffffu, sf[c][3], m1lane);
            float r0 = __shfl_sync(0xffffffffu, sf[c][0], m2lane);
            float r1 = __shfl_sync(0xffffffffu, sf[c][1], m2lane);
            float r2 = __shfl_sync(0xffffffffu, sf[c][2], m2lane);
            float r3 = __shfl_sync(0xffffffffu, sf[c][3], m2lane);
            uint32_t a0 = __float_as_uint(odd ? p1 : p0);
            uint32_t a1 = __float_as_uint(odd ? p3 : p2);
            uint32_t a2 = __float_as_uint(odd ? r1 : r0);
            uint32_t a3 = __float_as_uint(odd ? r3 : r2);
            #pragma unroll
            for (int f = 0; f < 8; f++) {
                const float* vb = &Vs[(f * 8 + g) * 68 + c * 8 + tg];
                mma_tf32(of[f][0], of[f][1], of[f][2], of[f][3],
                         a0, a1, a2, a3,
                         __float_as_uint(vb[0]), __float_as_uint(vb[4]));
            }
        }
        __syncthreads();
    }

    // Epilogue
    float i0 = 1.0f / l0, i1 = 1.0f / l1;
    int rlo = q0 + wm + g;
    #pragma unroll
    for (int f = 0; f < 8; f++) {
        int col = f * 8 + tg * 2;
        *(float2*)(O + base + (size_t)rlo * ND + col) =
            make_float2(of[f][0] * i0, of[f][1] * i0);
        *(float2*)(O + base + (size_t)(rlo + 8) * ND + col) =
            make_float2(of[f][2] * i1, of[f][3] * i1);
    }
}

// ---------------------------------------------------------------------------
extern "C" void kernel_launch(void* const* d_in, const int* in_sizes, int n_in,
                              void* d_out, int out_size)
{
    const float* x  = (const float*)d_in[0];
    const float* Wq = (const float*)d_in[1];
    const float* Wk = (const float*)d_in[2];
    const float* Wv = (const float*)d_in[3];
    const float* Wo = (const float*)d_in[4];
    float* out = (float*)d_out;

    float *pq, *pk, *pv, *pa, *pw;
    cudaGetSymbolAddress((void**)&pq, g_q);
    cudaGetSymbolAddress((void**)&pk, g_k);
    cudaGetSymbolAddress((void**)&pv, g_v);
    cudaGetSymbolAddress((void**)&pa, g_attn);
    cudaGetSymbolAddress((void**)&pw, g_wt);

    dim3 gt(32, 32), bt(32, 8);
    dim3 gg(ND / 128, NM / 128);  // (8, 32)

    transpose_w<<<gt, bt>>>(Wq, pw);
    gemm_tf32<<<gg, 256>>>(x, pw, pq, NM, ND, ND);
    transpose_w<<<gt, bt>>>(Wk, pw);
    gemm_tf32<<<gg, 256>>>(x, pw, pk, NM, ND, ND);
    transpose_w<<<gt, bt>>>(Wv, pw);
    gemm_tf32<<<gg, 256>>>(x, pw, pv, NM, ND, ND);

    transpose_v<<<dim3(NS / 32, NDK / 32, NB * NH), bt>>>();
    rope_kernel<<<(NM * (ND / 2)) / 256, 256>>>();

    size_t fsmem = (size_t)(128 * 68 + 64 * 68 + 64 * 68) * sizeof(float); // 69632
    cudaFuncSetAttribute(flash_tf32, cudaFuncAttributeMaxDynamicSharedMemorySize, (int)fsmem);
    flash_tf32<<<dim3(NS / 128, NB * NH), 256, fsmem>>>(pq, pk, pa);

    transpose_w<<<gt, bt>>>(Wo, pw);
    gemm_tf32<<<gg, 256>>>(pa, pw, out, NM, ND, ND);
}

// round 4
// speedup vs baseline: 3.2114x; 1.1165x over previous
#include <cuda_runtime.h>
#include <math.h>
#include <stdint.h>

#define NB 2
#define NS 2048
#define ND 1024
#define NH 16
#define NDK 64
#define NM (NB*NS)   // 4096

// Scratch (allocation-free)
__device__ float g_q[(size_t)NM * ND];
__device__ float g_k[(size_t)NM * ND];
__device__ float g_v[(size_t)NM * ND];
__device__ float g_attn[(size_t)NM * ND];
__device__ float g_xt[(size_t)NM * ND];          // x pre-rounded to tf32
__device__ float g_wt[4 * (size_t)ND * ND];      // 4 transposed tf32 weights
__device__ float g_vt[(size_t)NM * ND];          // V^T per head, tf32

__device__ __forceinline__ float to_tf32(float x)
{
    uint32_t u;
    asm("cvt.rna.tf32.f32 %0, %1;" : "=r"(u) : "f"(x));
    return __uint_as_float(u);
}

__device__ __forceinline__ void mma_tf32(float& d0, float& d1, float& d2, float& d3,
                                         uint32_t a0, uint32_t a1, uint32_t a2, uint32_t a3,
                                         uint32_t b0, uint32_t b1)
{
    asm volatile(
        "mma.sync.aligned.m16n8k8.row.col.f32.tf32.tf32.f32 "
        "{%0,%1,%2,%3}, {%4,%5,%6,%7}, {%8,%9}, {%0,%1,%2,%3};"
        : "+f"(d0), "+f"(d1), "+f"(d2), "+f"(d3)
        : "r"(a0), "r"(a1), "r"(a2), "r"(a3), "r"(b0), "r"(b1));
}

__device__ __forceinline__ void cp_async16(float* smem_dst, const float* gsrc)
{
    uint32_t s = (uint32_t)__cvta_generic_to_shared(smem_dst);
    asm volatile("cp.async.cg.shared.global [%0], [%1], 16;" :: "r"(s), "l"(gsrc));
}
__device__ __forceinline__ void cp_commit()
{
    asm volatile("cp.async.commit_group;");
}
__device__ __forceinline__ void cp_wait0()
{
    asm volatile("cp.async.wait_group 0;");
}

// ---------------------------------------------------------------------------
// x -> tf32 (one pass)
// ---------------------------------------------------------------------------
__global__ void cvt_x(const float* __restrict__ in)
{
    size_t i = ((size_t)blockIdx.x * 256 + threadIdx.x) * 4;
    float4 v = *(const float4*)(in + i);
    *(float4*)(&g_xt[i]) =
        make_float4(to_tf32(v.x), to_tf32(v.y), to_tf32(v.z), to_tf32(v.w));
}

// ---------------------------------------------------------------------------
// Transpose + tf32-round all 4 weights in one launch (z = which weight)
// ---------------------------------------------------------------------------
__global__ void transpose_w_cvt(const float* w0, const float* w1,
                                const float* w2, const float* w3)
{
    __shared__ float t[32][33];
    const float* in = (blockIdx.z == 0) ? w0 : (blockIdx.z == 1) ? w1
                    : (blockIdx.z == 2) ? w2 : w3;
    float* outp = g_wt + (size_t)blockIdx.z * ND * ND;
    int x = blockIdx.x * 32 + threadIdx.x;
    int y0 = blockIdx.y * 32;
    #pragma unroll
    for (int i = threadIdx.y; i < 32; i += 8)
        t[i][threadIdx.x] = in[(size_t)(y0 + i) * ND + x];
    __syncthreads();
    int ox = y0 + threadIdx.x;
    int oy0 = blockIdx.x * 32;
    #pragma unroll
    for (int i = threadIdx.y; i < 32; i += 8)
        outp[(size_t)(oy0 + i) * ND + ox] = to_tf32(t[threadIdx.x][i]);
}

// ---------------------------------------------------------------------------
// V transpose: g_vt[bh][d][s] = tf32(g_v[b][s][h*64+d])
// ---------------------------------------------------------------------------
__global__ void transpose_v()
{
    __shared__ float t[32][33];
    int bh = blockIdx.z;
    int b = bh >> 4, h = bh & 15;
    int s0 = blockIdx.x * 32, d0 = blockIdx.y * 32;
    #pragma unroll
    for (int i = threadIdx.y; i < 32; i += 8)
        t[i][threadIdx.x] = g_v[(size_t)(b * NS + s0 + i) * ND + h * NDK + d0 + threadIdx.x];
    __syncthreads();
    #pragma unroll
    for (int i = threadIdx.y; i < 32; i += 8)
        g_vt[((size_t)bh * NDK + d0 + i) * NS + s0 + threadIdx.x] =
            to_tf32(t[threadIdx.x][i]);
}

// ---------------------------------------------------------------------------
// RoPE: rotate Q,K; Q additionally scaled by 1/8; both emitted as tf32
// ---------------------------------------------------------------------------
__global__ void rope_kernel()
{
    const int NPAIR = ND / 2;
    int p = blockIdx.x * blockDim.x + threadIdx.x;
    if (p >= NM * NPAIR) return;
    int row = p / NPAIR;
    int pr  = p - row * NPAIR;
    int spos = row & (NS - 1);

    double fd = exp(((double)(-2 * pr) / (double)ND) * 9.210340371976184);
    float freq = (float)fd;
    float ang = (float)spos * freq;
    double sd, cd;
    sincos((double)ang, &sd, &cd);
    float sn = (float)sd, cs = (float)cd;

    size_t idx = (size_t)row * ND + 2 * pr;
    float2 q = *(float2*)(&g_q[idx]);
    float2 k = *(float2*)(&g_k[idx]);
    *(float2*)(&g_q[idx]) = make_float2(to_tf32((q.x * cs - q.y * sn) * 0.125f),
                                        to_tf32((q.x * sn + q.y * cs) * 0.125f));
    *(float2*)(&g_k[idx]) = make_float2(to_tf32(k.x * cs - k.y * sn),
                                        to_tf32(k.x * sn + k.y * cs));
}

// ---------------------------------------------------------------------------
// tf32 GEMM, cp.async double-buffered. Inputs already tf32.
// C[M,N]=A@W, Wt=W^T. 128x128 tile, 8 warps of 64x32, k-step 32.
// blockIdx.z selects weight slot & output (QKV fusion); smem stride 36.
// ---------------------------------------------------------------------------
#define GSLOT (128*36)

__global__ __launch_bounds__(256, 2)
void gemm_tf32(const float* __restrict__ A, int wslot,
               float* C0, float* C1, float* C2)
{
    extern __shared__ float gsm[];
    float* As = gsm;              // [2][128*36]
    float* Bs = gsm + 2 * GSLOT;  // [2][128*36]

    const int tid = threadIdx.x;
    const int warp = tid >> 5, lane = tid & 31;
    const int g = lane >> 2, tg = lane & 3;
    const int wm = (warp >> 2) << 6;
    const int wn = (warp & 3) << 5;

    const float* Wt = g_wt + (size_t)(wslot + blockIdx.z) * ND * ND;
    float* C = (blockIdx.z == 0) ? C0 : (blockIdx.z == 1) ? C1 : C2;

    const float* Ab = A + (size_t)(blockIdx.y * 128) * ND;
    const float* Bb = Wt + (size_t)(blockIdx.x * 128) * ND;

    float acc[4][4][4];
    #pragma unroll
    for (int mi = 0; mi < 4; mi++)
        #pragma unroll
        for (int ni = 0; ni < 4; ni++)
            #pragma unroll
            for (int r = 0; r < 4; r++) acc[mi][ni][r] = 0.0f;

    const int lr = tid >> 3;          // 0..31
    const int lc = (tid & 7) << 2;    // 0..28

    // preload k0 = 0 into buffer 0
    #pragma unroll
    for (int p = 0; p < 4; p++) {
        int row = lr + 32 * p;
        cp_async16(&As[row * 36 + lc], Ab + (size_t)row * ND + lc);
        cp_async16(&Bs[row * 36 + lc], Bb + (size_t)row * ND + lc);
    }
    cp_commit();

    int buf = 0;
    for (int k0 = 0; k0 < ND; k0 += 32) {
        cp_wait0();
        __syncthreads();

        if (k0 + 32 < ND) {
            int nb = buf ^ 1;
            #pragma unroll
            for (int p = 0; p < 4; p++) {
                int row = lr + 32 * p;
                cp_async16(&As[nb * GSLOT + row * 36 + lc],
                           Ab + (size_t)row * ND + k0 + 32 + lc);
                cp_async16(&Bs[nb * GSLOT + row * 36 + lc],
                           Bb + (size_t)row * ND + k0 + 32 + lc);
            }
            cp_commit();
        }

        const float* Ac = As + buf * GSLOT;
        const float* Bc = Bs + buf * GSLOT;
        #pragma unroll
        for (int c = 0; c < 4; c++) {
            uint32_t af[4][4];
            #pragma unroll
            for (int mi = 0; mi < 4; mi++) {
                const float* q = &Ac[(wm + mi * 16 + g) * 36 + c * 8 + tg];
                af[mi][0] = __float_as_uint(q[0]);
                af[mi][1] = __float_as_uint(q[8 * 36]);
                af[mi][2] = __float_as_uint(q[4]);
                af[mi][3] = __float_as_uint(q[8 * 36 + 4]);
            }
            #pragma unroll
            for (int ni = 0; ni < 4; ni++) {
                const float* q = &Bc[(wn + ni * 8 + g) * 36 + c * 8 + tg];
                uint32_t b0 = __float_as_uint(q[0]);
                uint32_t b1 = __float_as_uint(q[4]);
                #pragma unroll
                for (int mi = 0; mi < 4; mi++)
                    mma_tf32(acc[mi][ni][0], acc[mi][ni][1], acc[mi][ni][2], acc[mi][ni][3],
                             af[mi][0], af[mi][1], af[mi][2], af[mi][3], b0, b1);
            }
        }
        buf ^= 1;
    }

    #pragma unroll
    for (int mi = 0; mi < 4; mi++) {
        int row = blockIdx.y * 128 + wm + mi * 16 + g;
        #pragma unroll
        for (int ni = 0; ni < 4; ni++) {
            int col = blockIdx.x * 128 + wn + ni * 8 + tg * 2;
            *(float2*)(C + (size_t)row * ND + col) =
                make_float2(acc[mi][ni][0], acc[mi][ni][1]);
            *(float2*)(C + (size_t)(row + 8) * ND + col) =
                make_float2(acc[mi][ni][2], acc[mi][ni][3]);
        }
    }
}

// ---------------------------------------------------------------------------
// Flash attention, tf32 mma, cp.async double-buffered K/V.
// 128 q-rows/block, 64-kv tiles. Inputs pre-rounded (Q pre-scaled).
// ---------------------------------------------------------------------------
#define FKV (64*68)
extern __shared__ float fsm[];

__global__ __launch_bounds__(256)
void flash_tf32(const float* __restrict__ Q, const float* __restrict__ K,
                float* __restrict__ O)
{
    float* Qs = fsm;                    // [128][68]
    float* Ks = fsm + 128 * 68;         // [2][64][68]
    float* Vs = Ks + 2 * FKV;           // [2][64][68]

    const int tid = threadIdx.x;
    const int warp = tid >> 5, lane = tid & 31;
    const int g = lane >> 2, tg = lane & 3;
    const int qt = (int)gridDim.x - 1 - (int)blockIdx.x;
    const int bh = blockIdx.y;
    const int b = bh >> 4, h = bh & 15;
    const size_t base = (size_t)b * NS * ND + (size_t)h * NDK;
    const int q0 = qt * 128;
    const int wm = warp * 16;

    const int r = tid >> 4, c4 = (tid & 15) << 2;

    // Preload: Q tile (once) + K/V tile 0, all cp.async in group 0
    #pragma unroll
    for (int p = 0; p < 8; p++) {
        int row = r + 16 * p;
        cp_async16(&Qs[row * 68 + c4], Q + base + (size_t)(q0 + row) * ND + c4);
    }
    #pragma unroll
    for (int p = 0; p < 4; p++) {
        int row = r + 16 * p;
        cp_async16(&Ks[row * 68 + c4], K + base + (size_t)row * ND + c4);
        cp_async16(&Vs[row * 68 + c4], &g_vt[((size_t)bh * NDK + row) * NS + c4]);
    }
    cp_commit();

    float m0 = -INFINITY, m1 = -INFINITY, l0 = 0.0f, l1 = 0.0f;
    float of[8][4];
    #pragma unroll
    for (int f = 0; f < 8; f++)
        #pragma unroll
        for (int rr = 0; rr < 4; rr++) of[f][rr] = 0.0f;

    const int nt = 2 * qt + 2;
    int buf = 0;
    for (int t = 0; t < nt; t++) {
        cp_wait0();
        __syncthreads();

        if (t + 1 < nt) {
            int nb = buf ^ 1;
            int kn = 64 * (t + 1);
            #pragma unroll
            for (int p = 0; p < 4; p++) {
                int row = r + 16 * p;
                cp_async16(&Ks[nb * FKV + row * 68 + c4],
                           K + base + (size_t)(kn + row) * ND + c4);
                cp_async16(&Vs[nb * FKV + row * 68 + c4],
                           &g_vt[((size_t)bh * NDK + row) * NS + kn + c4]);
            }
            cp_commit();
        }

        const float* Kc = Ks + buf * FKV;
        const float* Vc = Vs + buf * FKV;
        const int k0 = 64 * t;

        // S = Q K^T
        float sf[8][4];
        #pragma unroll
        for (int f = 0; f < 8; f++)
            #pragma unroll
            for (int rr = 0; rr < 4; rr++) sf[f][rr] = 0.0f;

        #pragma unroll
        for (int c = 0; c < 8; c++) {
            const float* qa = &Qs[(wm + g) * 68 + c * 8 + tg];
            uint32_t a0 = __float_as_uint(qa[0]);
            uint32_t a1 = __float_as_uint(qa[8 * 68]);
            uint32_t a2 = __float_as_uint(qa[4]);
            uint32_t a3 = __float_as_uint(qa[8 * 68 + 4]);
            #pragma unroll
            for (int f = 0; f < 8; f++) {
                const float* kb = &Kc[(f * 8 + g) * 68 + c * 8 + tg];
                mma_tf32(sf[f][0], sf[f][1], sf[f][2], sf[f][3],
                         a0, a1, a2, a3,
                         __float_as_uint(kb[0]), __float_as_uint(kb[4]));
            }
        }

        if (t >= 2 * qt) {   // diagonal tiles: causal mask
            int rlo = q0 + wm + g, rhi = rlo + 8;
            #pragma unroll
            for (int f = 0; f < 8; f++) {
                int col = k0 + f * 8 + tg * 2;
                if (col     > rlo) sf[f][0] = -INFINITY;
                if (col + 1 > rlo) sf[f][1] = -INFINITY;
                if (col     > rhi) sf[f][2] = -INFINITY;
                if (col + 1 > rhi) sf[f][3] = -INFINITY;
            }
        }

        // Online softmax
        float mx0 = -INFINITY, mx1 = -INFINITY;
        #pragma unroll
        for (int f = 0; f < 8; f++) {
            mx0 = fmaxf(mx0, fmaxf(sf[f][0], sf[f][1]));
            mx1 = fmaxf(mx1, fmaxf(sf[f][2], sf[f][3]));
        }
        mx0 = fmaxf(mx0, __shfl_xor_sync(0xffffffffu, mx0, 1));
        mx0 = fmaxf(mx0, __shfl_xor_sync(0xffffffffu, mx0, 2));
        mx1 = fmaxf(mx1, __shfl_xor_sync(0xffffffffu, mx1, 1));
        mx1 = fmaxf(mx1, __shfl_xor_sync(0xffffffffu, mx1, 2));
        float mn0 = fmaxf(m0, mx0), mn1 = fmaxf(m1, mx1);
        float s0 = 0.0f, s1 = 0.0f;
        #pragma unroll
        for (int f = 0; f < 8; f++) {
            sf[f][0] = __expf(sf[f][0] - mn0); s0 += sf[f][0];
            sf[f][1] = __expf(sf[f][1] - mn0); s0 += sf[f][1];
            sf[f][2] = __expf(sf[f][2] - mn1); s1 += sf[f][2];
            sf[f][3] = __expf(sf[f][3] - mn1); s1 += sf[f][3];
        }
        s0 += __shfl_xor_sync(0xffffffffu, s0, 1);
        s0 += __shfl_xor_sync(0xffffffffu, s0, 2);
        s1 += __shfl_xor_sync(0xffffffffu, s1, 1);
        s1 += __shfl_xor_sync(0xffffffffu, s1, 2);
        float e0 = __expf(m0 - mn0), e1 = __expf(m1 - mn1);
        l0 = l0 * e0 + s0; l1 = l1 * e1 + s1;
        m0 = mn0; m1 = mn1;
        #pragma unroll
        for (int f = 0; f < 8; f++) {
            of[f][0] *= e0; of[f][1] *= e0;
            of[f][2] *= e1; of[f][3] *= e1;
        }

        // P -> tf32
        #pragma unroll
        for (int f = 0; f < 8; f++)
            #pragma unroll
            for (int rr = 0; rr < 4; rr++) sf[f][rr] = to_tf32(sf[f][rr]);

        // O += P V (A-frags via intra-quad shuffles)
        const int m1lane = (lane & ~3) | (tg >> 1);
        const int m2lane = m1lane + 2;
        const bool odd = (tg & 1);
        #pragma unroll
        for (int c = 0; c < 8; c++) {
            float p0 = __shfl_sync(0xffffffffu, sf[c][0], m1lane);
            float p1 = __shfl_sync(0xffffffffu, sf[c][1], m1lane);
            float p2 = __shfl_sync(0xffffffffu, sf[c][2], m1lane);
            float p3 = __shfl_sync(0xffffffffu, sf[c][3], m1lane);
            float r0 = __shfl_sync(0xffffffffu, sf[c][0], m2lane);
            float r1 = __shfl_sync(0xffffffffu, sf[c][1], m2lane);
            float r2 = __shfl_sync(0xffffffffu, sf[c][2], m2lane);
            float r3 = __shfl_sync(0xffffffffu, sf[c][3], m2lane);
            uint32_t a0 = __float_as_uint(odd ? p1 : p0);
            uint32_t a1 = __float_as_uint(odd ? p3 : p2);
            uint32_t a2 = __float_as_uint(odd ? r1 : r0);
            uint32_t a3 = __float_as_uint(odd ? r3 : r2);
            #pragma unroll
            for (int f = 0; f < 8; f++) {
                const float* vb = &Vc[(f * 8 + g) * 68 + c * 8 + tg];
                mma_tf32(of[f][0], of[f][1], of[f][2], of[f][3],
                         a0, a1, a2, a3,
                         __float_as_uint(vb[0]), __float_as_uint(vb[4]));
            }
        }
        buf ^= 1;
    }

    // Epilogue: normalize, round to tf32 (input of final GEMM)
    float i0 = 1.0f / l0, i1 = 1.0f / l1;
    int rlo = q0 + wm + g;
    #pragma unroll
    for (int f = 0; f < 8; f++) {
        int col = f * 8 + tg * 2;
        *(float2*)(O + base + (size_t)rlo * ND + col) =
            make_float2(to_tf32(of[f][0] * i0), to_tf32(of[f][1] * i0));
        *(float2*)(O + base + (size_t)(rlo + 8) * ND + col) =
            make_float2(to_tf32(of[f][2] * i1), to_tf32(of[f][3] * i1));
    }
}

// ---------------------------------------------------------------------------
extern "C" void kernel_launch(void* const* d_in, const int* in_sizes, int n_in,
                              void* d_out, int out_size)
{
    const float* x  = (const float*)d_in[0];
    const float* Wq = (const float*)d_in[1];
    const float* Wk = (const float*)d_in[2];
    const float* Wv = (const float*)d_in[3];
    const float* Wo = (const float*)d_in[4];
    float* out = (float*)d_out;

    float *pq, *pk, *pv, *pa, *pxt;
    cudaGetSymbolAddress((void**)&pq, g_q);
    cudaGetSymbolAddress((void**)&pk, g_k);
    cudaGetSymbolAddress((void**)&pv, g_v);
    cudaGetSymbolAddress((void**)&pa, g_attn);
    cudaGetSymbolAddress((void**)&pxt, g_xt);

    size_t gsmem = (size_t)4 * GSLOT * sizeof(float);            // 73728
    size_t fsmem = (size_t)(128 * 68 + 4 * FKV) * sizeof(float); // 104448
    cudaFuncSetAttribute(gemm_tf32, cudaFuncAttributeMaxDynamicSharedMemorySize, (int)gsmem);
    cudaFuncSetAttribute(flash_tf32, cudaFuncAttributeMaxDynamicSharedMemorySize, (int)fsmem);

    dim3 bt(32, 8);

    cvt_x<<<(NM * ND) / 1024, 256>>>(x);
    transpose_w_cvt<<<dim3(32, 32, 4), bt>>>(Wq, Wk, Wv, Wo);

    // QKV fused: z = 0,1,2 -> weight slots 0..2
    gemm_tf32<<<dim3(8, 32, 3), 256, gsmem>>>(pxt, 0, pq, pk, pv);

    transpose_v<<<dim3(NS / 32, NDK / 32, NB * NH), bt>>>();
    rope_kernel<<<(NM * (ND / 2)) / 256, 256>>>();

    flash_tf32<<<dim3(NS / 128, NB * NH), 256, fsmem>>>(pq, pk, pa);

    // Output projection: weight slot 3
    gemm_tf32<<<dim3(8, 32, 1), 256, gsmem>>>(pa, 3, out, out, out);
}